// round 2
// baseline (speedup 1.0000x reference)
#include <cuda_runtime.h>
#include <cstdint>
#include <cstddef>

#define NB   32
#define NS   512
#define ND   512
#define NH2  256
#define NG3  768
#define NDK  64

// ------------------------- scratch (device globals) -------------------------
__device__ float g_xg[(size_t)2 * NB * NS * NG3];   // gate preactivations, per dir
__device__ float g_gru[(size_t)NB * NS * ND];       // concat GRU outputs
__device__ float g_ln1[(size_t)NB * NS * ND];       // ln1("outputs")
__device__ float g_q [(size_t)NB * 8 * NS * NDK];   // (b,h,s,d)
__device__ float g_k [(size_t)NB * 8 * NS * NDK];   // (b,h,s,d)
__device__ float g_vt[(size_t)NB * 8 * NDK * NS];   // (b,h,d,s)
__device__ float g_sc[(size_t)NB * 8 * NS * NS];    // scores -> p
__device__ float g_cc[(size_t)NB * NS * ND];        // attn concat
__device__ float g_o [(size_t)NB * NS * ND];        // out projection
__device__ float g_hx[16 * 2048];                   // h exchange (16 groups x 2 bufs x 1024)
__device__ unsigned g_cnt[32];                      // group step counters

// ------------------------- f32x2 helpers -------------------------
__device__ __forceinline__ unsigned long long fma2(unsigned long long a,
                                                   unsigned long long b,
                                                   unsigned long long c) {
    unsigned long long d;
    asm("fma.rn.f32x2 %0, %1, %2, %3;" : "=l"(d) : "l"(a), "l"(b), "l"(c));
    return d;
}
__device__ __forceinline__ unsigned long long pack2(float x, float y) {
    unsigned long long d;
    asm("mov.b64 %0, {%1, %2};" : "=l"(d) : "f"(x), "f"(y));
    return d;
}
__device__ __forceinline__ void unpack2(unsigned long long v, float& x, float& y) {
    asm("mov.b64 {%0, %1}, %2;" : "=f"(x), "=f"(y) : "l"(v));
}

// ------------------------- generic TN GEMM -------------------------
// C = epi(A[M,K] @ W[N,K]^T). modes:
// 0: +bias              1: +bias, scatter (b,h,s,d)   2: +bias, scatter (b,h,d,s)
// 3: *scale             4: scatter concat (b,s,h*64+d) 5: +bias, *rowmask(masks)
__device__ __forceinline__ void store_elem(float* C, const float* bias,
                                           const int* masks, int mode, float scale,
                                           int z, int N, int mrow, int nc, float v) {
    if (nc >= N) return;
    if (mode == 0) {
        C[(long)mrow * N + nc] = v + bias[nc];
    } else if (mode == 1) {
        int b = mrow >> 9, s = mrow & 511, h = nc >> 6, d = nc & 63;
        C[(((long)(b * 8 + h) * NS + s)) * NDK + d] = v + bias[nc];
    } else if (mode == 2) {
        int b = mrow >> 9, s = mrow & 511, h = nc >> 6, d = nc & 63;
        C[((long)(b * 8 + h) * NDK + d) * NS + s] = v + bias[nc];
    } else if (mode == 3) {
        C[(long)mrow * N + nc] = v * scale;
    } else if (mode == 4) {
        int b = z >> 3, h = z & 7;
        C[((long)(b * NS + mrow)) * ND + h * NDK + nc] = v;
    } else {
        C[(long)mrow * N + nc] = masks[mrow] ? (v + bias[nc]) : 0.f;
    }
}

__global__ void __launch_bounds__(256) gemm_tn(
    const float* __restrict__ A, const float* __restrict__ W,
    const float* __restrict__ bias, float* __restrict__ C,
    int M, int N, int K, long sA, long sW, long sC,
    int mode, float scale, const int* __restrict__ masks)
{
    __shared__ float As[8][128];
    __shared__ float Ws[8][128];

    const int z = blockIdx.z;
    A += (long)z * sA;
    W += (long)z * sW;
    if (mode == 0 || mode == 3) C += (long)z * sC;

    const int m0 = blockIdx.y * 128, n0 = blockIdx.x * 128;
    const int tid = threadIdx.x;
    const int lrow = tid >> 1, lkq = tid & 1;
    const int tx = tid & 15, ty = tid >> 4;
    const bool wok = (n0 + lrow) < N;
    const float* Ap = A + (long)(m0 + lrow) * K + lkq * 4;
    const float* Wp = W + (long)(n0 + lrow) * K + lkq * 4;

    unsigned long long acc[8][4];
#pragma unroll
    for (int i = 0; i < 8; i++) {
        acc[i][0] = 0ull; acc[i][1] = 0ull; acc[i][2] = 0ull; acc[i][3] = 0ull;
    }

    float4 av = *(const float4*)Ap;
    float4 wv = wok ? *(const float4*)Wp : make_float4(0.f, 0.f, 0.f, 0.f);

    for (int k0 = 0; k0 < K; k0 += 8) {
        __syncthreads();
        As[lkq * 4 + 0][lrow] = av.x; As[lkq * 4 + 1][lrow] = av.y;
        As[lkq * 4 + 2][lrow] = av.z; As[lkq * 4 + 3][lrow] = av.w;
        Ws[lkq * 4 + 0][lrow] = wv.x; Ws[lkq * 4 + 1][lrow] = wv.y;
        Ws[lkq * 4 + 2][lrow] = wv.z; Ws[lkq * 4 + 3][lrow] = wv.w;
        __syncthreads();
        if (k0 + 8 < K) {
            av = *(const float4*)(Ap + k0 + 8);
            wv = wok ? *(const float4*)(Wp + k0 + 8) : make_float4(0.f, 0.f, 0.f, 0.f);
        }
#pragma unroll
        for (int kk = 0; kk < 8; kk++) {
            float4 a0 = *(const float4*)&As[kk][ty * 4];
            float4 a1 = *(const float4*)&As[kk][ty * 4 + 64];
            ulonglong2 w0 = *(const ulonglong2*)&Ws[kk][tx * 4];
            ulonglong2 w1 = *(const ulonglong2*)&Ws[kk][tx * 4 + 64];
            unsigned long long ap[8];
            ap[0] = pack2(a0.x, a0.x); ap[1] = pack2(a0.y, a0.y);
            ap[2] = pack2(a0.z, a0.z); ap[3] = pack2(a0.w, a0.w);
            ap[4] = pack2(a1.x, a1.x); ap[5] = pack2(a1.y, a1.y);
            ap[6] = pack2(a1.z, a1.z); ap[7] = pack2(a1.w, a1.w);
#pragma unroll
            for (int i = 0; i < 8; i++) {
                acc[i][0] = fma2(ap[i], w0.x, acc[i][0]);
                acc[i][1] = fma2(ap[i], w0.y, acc[i][1]);
                acc[i][2] = fma2(ap[i], w1.x, acc[i][2]);
                acc[i][3] = fma2(ap[i], w1.y, acc[i][3]);
            }
        }
    }

#pragma unroll
    for (int i = 0; i < 8; i++) {
        int mrow = m0 + ty * 4 + (i & 3) + (i >> 2) * 64;
#pragma unroll
        for (int jp = 0; jp < 4; jp++) {
            float lo, hi;
            unpack2(acc[i][jp], lo, hi);
            int nc = n0 + tx * 4 + (jp & 1) * 2 + (jp >> 1) * 64;
            store_elem(C, bias, masks, mode, scale, z, N, mrow, nc, lo);
            store_elem(C, bias, masks, mode, scale, z, N, mrow, nc + 1, hi);
        }
    }
}

// ------------------------- counter reset -------------------------
__global__ void reset_kernel() {
    if (threadIdx.x < 32) g_cnt[threadIdx.x] = 0u;
}

// ------------------------- persistent GRU -------------------------
// 128 blocks = dir(2) x batchgroup(8 of 4 batches) x jchunk(8 of 32 j).
// 384 threads: (r in [0,96)) x (kq in [0,4)); recurrent weights register-resident.
// h exchanged across the 8 j-chunk blocks of a group via L2 + counter spin.
__global__ void __launch_bounds__(384, 1) gru_kernel(
    const float* __restrict__ whf, const float* __restrict__ whb,
    const float* __restrict__ bhf, const float* __restrict__ bhb,
    const int* __restrict__ masks, float* __restrict__ hid_out)
{
    __shared__ float sh_h[1024];     // [b][k] full h for 4 batches
    __shared__ float sh_part[1536];  // [r][b][kq]
    __shared__ float sh_gate[384];   // [r][b]

    const int bid = blockIdx.x;
    const int dir = bid >> 6;
    const int rem = bid & 63;
    const int bg  = rem >> 3;
    const int jc  = rem & 7;
    const int tid = threadIdx.x;
    const int r   = tid >> 2;        // 0..95 (gate-row in block)
    const int kq  = tid & 3;         // k quarter
    const int G   = (r >> 5) * 256 + jc * 32 + (r & 31);

    const float* wh = dir ? whb : whf;
    const float* bh = dir ? bhb : bhf;
    const float bhh = bh[G];

    unsigned long long wp[32];
    {
        const float* ws = wh + (long)G * NH2 + kq * 64;
#pragma unroll
        for (int i = 0; i < 32; i++) wp[i] = pack2(ws[2 * i], ws[2 * i + 1]);
    }

    const int ju = tid & 31, bu = tid >> 5;   // updater role (tid < 128)
    const int jglob = jc * 32 + ju;
    const int bglob = bg * 4 + bu;
    const float* xgp = g_xg + ((size_t)dir * NB + bglob) * NS * NG3;
    float* hxg = g_hx + (dir * 8 + bg) * 2048;
    unsigned* cnt = &g_cnt[dir * 8 + bg];

    for (int i = tid; i < 1024; i += 384) sh_h[i] = 0.f;
    float hreg = 0.f;
    __syncthreads();

    for (int t = 0; t < NS; t++) {
        const int s = dir ? (NS - 1 - t) : t;
        float xr = 0.f, xz = 0.f, xn = 0.f;
        int mk = 0;
        if (tid < 128) {  // prefetch x-gates + mask (independent of h)
            const float* xrow = xgp + (size_t)s * NG3;
            xr = __ldg(xrow + jglob);
            xz = __ldg(xrow + NH2 + jglob);
            xn = __ldg(xrow + 2 * NH2 + jglob);
            mk = __ldg(masks + bglob * NS + s);
        }
        if (t > 0) {
            if (tid == 0) {
                const unsigned target = 8u * (unsigned)t;
                unsigned v;
                do {
                    asm volatile("ld.global.cg.u32 %0, [%1];" : "=r"(v) : "l"(cnt) : "memory");
                    if (v >= target) break;
                    __nanosleep(64);
                } while (1);
                __threadfence();
            }
            __syncthreads();
            const float* src = hxg + ((t - 1) & 1) * 1024;
            for (int i = tid; i < 1024; i += 384) sh_h[i] = __ldcg(src + i);
            __syncthreads();
        }
        // hg partial dot products (f32x2)
        unsigned long long acc[4] = {0ull, 0ull, 0ull, 0ull};
#pragma unroll
        for (int i = 0; i < 16; i++) {
#pragma unroll
            for (int b = 0; b < 4; b++) {
                ulonglong2 hv = *(const ulonglong2*)(sh_h + b * 256 + kq * 64 + i * 4);
                acc[b] = fma2(wp[2 * i],     hv.x, acc[b]);
                acc[b] = fma2(wp[2 * i + 1], hv.y, acc[b]);
            }
        }
#pragma unroll
        for (int b = 0; b < 4; b++) {
            float lo, hi;
            unpack2(acc[b], lo, hi);
            sh_part[r * 16 + b * 4 + kq] = lo + hi;
        }
        __syncthreads();
        {   // k-quarter reduction: thread -> (r, b2=kq)
            const int base = r * 16 + kq * 4;
            sh_gate[r * 4 + kq] = sh_part[base] + sh_part[base + 1] +
                                  sh_part[base + 2] + sh_part[base + 3] + bhh;
        }
        __syncthreads();
        if (tid < 128) {
            const float hgr = sh_gate[ju * 4 + bu];
            const float hgz = sh_gate[(32 + ju) * 4 + bu];
            const float hgn = sh_gate[(64 + ju) * 4 + bu];
            const float rr = 1.f / (1.f + __expf(-(xr + hgr)));
            const float zz = 1.f / (1.f + __expf(-(xz + hgz)));
            const float na = xn + rr * hgn;
            const float nn = 2.f / (1.f + __expf(-2.f * na)) - 1.f;  // tanh
            const float hnew = (1.f - zz) * nn + zz * hreg;
            hreg = mk ? hnew : hreg;
            g_gru[((size_t)bglob * NS + s) * ND + dir * NH2 + jglob] = mk ? hreg : 0.f;
            if (t == NS - 1)
                hid_out[bglob * ND + dir * NH2 + jglob] = hreg;
            else
                __stcg(hxg + (t & 1) * 1024 + bu * 256 + jglob, hreg);
        }
        if (t < NS - 1) {
            __threadfence();
            __syncthreads();
            if (tid == 0) atomicAdd(cnt, 1u);
        }
    }
}

// ------------------------- layernorm (optionally fused residual) -------------------------
__global__ void __launch_bounds__(128) ln_kernel(
    const float* __restrict__ x, const float* __restrict__ y,
    const float* __restrict__ gam, const float* __restrict__ bet,
    float* __restrict__ out)
{
    __shared__ float red[8];
    const int row = blockIdx.x;
    const int tid = threadIdx.x;
    float4 v = *(const float4*)(x + (size_t)row * ND + tid * 4);
    if (y) {
        float4 w = *(const float4*)(y + (size_t)row * ND + tid * 4);
        v.x += w.x; v.y += w.y; v.z += w.z; v.w += w.w;
    }
    float s1 = v.x + v.y + v.z + v.w;
    float s2 = v.x * v.x + v.y * v.y + v.z * v.z + v.w * v.w;
#pragma unroll
    for (int o = 16; o; o >>= 1) {
        s1 += __shfl_xor_sync(~0u, s1, o);
        s2 += __shfl_xor_sync(~0u, s2, o);
    }
    const int wid = tid >> 5;
    if ((tid & 31) == 0) { red[wid] = s1; red[wid + 4] = s2; }
    __syncthreads();
    s1 = red[0] + red[1] + red[2] + red[3];
    s2 = red[4] + red[5] + red[6] + red[7];
    const float mu = s1 * (1.f / ND);
    const float var = s2 * (1.f / ND) - mu * mu;
    const float rs = rsqrtf(var + 1e-5f);
    const float4 gv = *(const float4*)(gam + tid * 4);
    const float4 bv = *(const float4*)(bet + tid * 4);
    float4 o4;
    o4.x = (v.x - mu) * rs * gv.x + bv.x;
    o4.y = (v.y - mu) * rs * gv.y + bv.y;
    o4.z = (v.z - mu) * rs * gv.z + bv.z;
    o4.w = (v.w - mu) * rs * gv.w + bv.w;
    *(float4*)(out + (size_t)row * ND + tid * 4) = o4;
}

// ------------------------- masked prefix softmax -------------------------
__global__ void __launch_bounds__(128) softmax_kernel(
    float* __restrict__ P, const int* __restrict__ lengths)
{
    __shared__ float red[4];
    const int q = blockIdx.x, z = blockIdx.y;
    const int len = __ldg(lengths + (z >> 3));
    float* row = P + ((size_t)z * NS + q) * NS;
    const int tid = threadIdx.x;
    const int c0 = tid * 4;
    if (q >= len) {
        *(float4*)(row + c0) = make_float4(0.f, 0.f, 0.f, 0.f);
        return;
    }
    float4 v = *(const float4*)(row + c0);
    const bool b0 = c0 < len, b1 = c0 + 1 < len, b2 = c0 + 2 < len, b3 = c0 + 3 < len;
    float m = -1e30f;
    if (b0) m = fmaxf(m, v.x);
    if (b1) m = fmaxf(m, v.y);
    if (b2) m = fmaxf(m, v.z);
    if (b3) m = fmaxf(m, v.w);
#pragma unroll
    for (int o = 16; o; o >>= 1) m = fmaxf(m, __shfl_xor_sync(~0u, m, o));
    const int wid = tid >> 5;
    if ((tid & 31) == 0) red[wid] = m;
    __syncthreads();
    m = fmaxf(fmaxf(red[0], red[1]), fmaxf(red[2], red[3]));
    __syncthreads();
    float4 e;
    e.x = b0 ? __expf(v.x - m) : 0.f;
    e.y = b1 ? __expf(v.y - m) : 0.f;
    e.z = b2 ? __expf(v.z - m) : 0.f;
    e.w = b3 ? __expf(v.w - m) : 0.f;
    float s = e.x + e.y + e.z + e.w;
#pragma unroll
    for (int o = 16; o; o >>= 1) s += __shfl_xor_sync(~0u, s, o);
    if ((tid & 31) == 0) red[wid] = s;
    __syncthreads();
    s = red[0] + red[1] + red[2] + red[3];
    const float inv = 1.f / s;
    e.x *= inv; e.y *= inv; e.z *= inv; e.w *= inv;
    *(float4*)(row + c0) = e;
}

// ------------------------- launch -------------------------
extern "C" void kernel_launch(void* const* d_in, const int* in_sizes, int n_in,
                              void* d_out, int out_size)
{
    const float* splits = (const float*)d_in[0];
    const float* w_ih_f = (const float*)d_in[1];
    const float* w_hh_f = (const float*)d_in[2];
    const float* b_ih_f = (const float*)d_in[3];
    const float* b_hh_f = (const float*)d_in[4];
    const float* w_ih_b = (const float*)d_in[5];
    const float* w_hh_b = (const float*)d_in[6];
    const float* b_ih_b = (const float*)d_in[7];
    const float* b_hh_b = (const float*)d_in[8];
    const float* ln1_g  = (const float*)d_in[9];
    const float* ln1_b  = (const float*)d_in[10];
    const float* wq = (const float*)d_in[11];
    const float* bq = (const float*)d_in[12];
    const float* wk = (const float*)d_in[13];
    const float* bk = (const float*)d_in[14];
    const float* wv = (const float*)d_in[15];
    const float* bv = (const float*)d_in[16];
    const float* wo = (const float*)d_in[17];
    const float* bo = (const float*)d_in[18];
    const float* ln2_g = (const float*)d_in[19];
    const float* ln2_b = (const float*)d_in[20];
    const int* lengths = (const int*)d_in[21];
    const int* masks   = (const int*)d_in[22];
    float* out = (float*)d_out;

    float *xg, *gru, *ln1, *q, *k, *vt, *sc, *cc, *oo;
    cudaGetSymbolAddress((void**)&xg,  g_xg);
    cudaGetSymbolAddress((void**)&gru, g_gru);
    cudaGetSymbolAddress((void**)&ln1, g_ln1);
    cudaGetSymbolAddress((void**)&q,   g_q);
    cudaGetSymbolAddress((void**)&k,   g_k);
    cudaGetSymbolAddress((void**)&vt,  g_vt);
    cudaGetSymbolAddress((void**)&sc,  g_sc);
    cudaGetSymbolAddress((void**)&cc,  g_cc);
    cudaGetSymbolAddress((void**)&oo,  g_o);

    const int M = NB * NS;  // 16384

    // GRU input projections (both dirs)
    gemm_tn<<<dim3(6, 128, 1), 256>>>(splits, w_ih_f, b_ih_f, xg,
                                      M, NG3, ND, 0, 0, 0, 0, 1.f, nullptr);
    gemm_tn<<<dim3(6, 128, 1), 256>>>(splits, w_ih_b, b_ih_b, xg + (size_t)M * NG3,
                                      M, NG3, ND, 0, 0, 0, 0, 1.f, nullptr);
    // GRU recurrence (persistent, inter-block L2 sync)
    reset_kernel<<<1, 32>>>();
    gru_kernel<<<128, 384>>>(w_hh_f, w_hh_b, b_hh_f, b_hh_b, masks,
                             out + (size_t)NB * NS * ND);
    // LN1
    ln_kernel<<<M, 128>>>(gru, nullptr, ln1_g, ln1_b, ln1);
    // Q/K/V projections with head scatter
    gemm_tn<<<dim3(4, 128, 1), 256>>>(ln1, wq, bq, q,  M, ND, ND, 0, 0, 0, 1, 1.f, nullptr);
    gemm_tn<<<dim3(4, 128, 1), 256>>>(ln1, wk, bk, k,  M, ND, ND, 0, 0, 0, 1, 1.f, nullptr);
    gemm_tn<<<dim3(4, 128, 1), 256>>>(ln1, wv, bv, vt, M, ND, ND, 0, 0, 0, 2, 1.f, nullptr);
    // scores = q @ k^T / 8   (z = b*8+h)
    gemm_tn<<<dim3(4, 4, 256), 256>>>(q, k, nullptr, sc, NS, NS, NDK,
                                      (long)NS * NDK, (long)NS * NDK, (long)NS * NS,
                                      3, 0.125f, nullptr);
    // masked prefix softmax (in place)
    softmax_kernel<<<dim3(NS, 256), 128>>>(sc, lengths);
    // attn = p @ v  -> concat layout
    gemm_tn<<<dim3(1, 4, 256), 256>>>(sc, vt, nullptr, cc, NS, NDK, NS,
                                      (long)NS * NS, (long)NS * NDK, 0,
                                      4, 1.f, nullptr);
    // out projection + row mask
    gemm_tn<<<dim3(4, 128, 1), 256>>>(cc, wo, bo, oo, M, ND, ND, 0, 0, 0, 5, 1.f, masks);
    // residual + LN2 -> final outputs
    ln_kernel<<<M, 128>>>(ln1, oo, ln2_g, ln2_b, out);
}